// round 15
// baseline (speedup 1.0000x reference)
#include <cuda_runtime.h>
#include <cstdint>

#define BB 4
#define SS_ 2048
#define EE 1024
#define HH 128

#define NEG_INF (-1e30f)
#define QSCALE 0.08838834764831845f   // 1/sqrt(128)

// Scratch (device globals).  g_q/g_k: [b][s][h] pre-rounded tf32 (q pre-scaled).
// g_v: TRANSPOSED [b][h][s], pre-rounded tf32 (for ldmatrix-friendly V tiles).
__device__ float g_q[BB * SS_ * HH];
__device__ float g_k[BB * SS_ * HH];
__device__ float g_v[BB * SS_ * HH];

// ---------------------------------------------------------------------------
// Helpers
// ---------------------------------------------------------------------------
__device__ __forceinline__ uint32_t smem_u32(const void* p) {
    uint32_t a;
    asm("{ .reg .u64 t; cvta.to.shared.u64 t, %1; cvt.u32.u64 %0, t; }"
        : "=r"(a) : "l"(p));
    return a;
}
__device__ __forceinline__ uint32_t f2tf32(float f) {
    uint32_t r;
    asm("cvt.rna.tf32.f32 %0, %1;" : "=r"(r) : "f"(f));
    return r;
}
__device__ __forceinline__ void mma_tf32(float* d, const uint32_t* a,
                                         const uint32_t* b) {
    asm volatile(
        "mma.sync.aligned.m16n8k8.row.col.f32.tf32.tf32.f32 "
        "{%0,%1,%2,%3}, {%4,%5,%6,%7}, {%8,%9}, {%0,%1,%2,%3};"
        : "+f"(d[0]), "+f"(d[1]), "+f"(d[2]), "+f"(d[3])
        : "r"(a[0]), "r"(a[1]), "r"(a[2]), "r"(a[3]), "r"(b[0]), "r"(b[1]));
}
// ldmatrix x4 on 8x4-tf32 (16B-row) tiles: reg i = fragment of matrix i,
// thread l holds word (row l/4, col l%4) — exactly the tf32 mma layout.
__device__ __forceinline__ void ldsm_x4(uint32_t& r0, uint32_t& r1,
                                        uint32_t& r2, uint32_t& r3,
                                        uint32_t addr) {
    asm volatile("ldmatrix.sync.aligned.m8n8.x4.shared.b16 {%0,%1,%2,%3}, [%4];"
                 : "=r"(r0), "=r"(r1), "=r"(r2), "=r"(r3) : "r"(addr));
}
#define CP_ASYNC16(dst_u32, src) \
    asm volatile("cp.async.cg.shared.global [%0], [%1], 16;" :: "r"(dst_u32), "l"(src))
#define CP_COMMIT() asm volatile("cp.async.commit_group;" ::: "memory")
#define CP_WAIT(n)  asm volatile("cp.async.wait_group %0;" :: "n"(n) : "memory")
#define BAR_SYNC(id, n) asm volatile("bar.sync %0, %1;" :: "r"(id), "r"(n) : "memory")

// ---------------------------------------------------------------------------
// Fused projection GEMM (R12 core): O[M,384] = X[M,E] @ [Wq|Wk|Wv].
// Epilogue: q/k stored [b][s][h]; V stored TRANSPOSED [b][h][s].
// ---------------------------------------------------------------------------
#define PBM 64
#define PBK 16
#define SA_STR 20
#define SB_STR 392
#define PROJ_SMEM ((2 * PBM * SA_STR + 2 * PBK * SB_STR) * 4)  // 60416 B
#define NIT (EE / PBK)   // 64

__global__ __launch_bounds__(256, 1) void proj_mma_kernel(
    const float* __restrict__ x,
    const float* __restrict__ Wq,
    const float* __restrict__ Wk,
    const float* __restrict__ Wv)
{
    extern __shared__ float psm[];
    float* sA = psm;                        // [2][64*20]
    float* sB = psm + 2 * PBM * SA_STR;     // [2][16*392]

    const int m0   = blockIdx.x * PBM;
    const int tid  = threadIdx.x;
    const int wid  = tid >> 5;
    const int lane = tid & 31;
    const int g    = lane >> 2;
    const int tig  = lane & 3;
    const int wm   = wid & 1;
    const int wn   = wid >> 1;

    const float* __restrict__ Ws[3] = {Wq, Wk, Wv};

    auto load_tiles = [&](int st, int k0) {
        {
            int r = tid >> 2, qa = tid & 3;
            CP_ASYNC16(smem_u32(&sA[st * PBM * SA_STR + r * SA_STR + qa * 4]),
                       x + (size_t)(m0 + r) * EE + k0 + qa * 4);
        }
#pragma unroll
        for (int p = 0; p < 6; p++) {
            int idx = p * 256 + tid;
            int row = idx / 96, q = idx % 96;
            int col4 = q * 4;
            const float* W = Ws[col4 >> 7];
            int wcol = col4 & 127;
            CP_ASYNC16(smem_u32(&sB[st * PBK * SB_STR + row * SB_STR + col4]),
                       W + (size_t)(k0 + row) * HH + wcol);
        }
    };

    float acc[2][12][4];
#pragma unroll
    for (int i = 0; i < 2; i++)
#pragma unroll
        for (int j = 0; j < 12; j++)
#pragma unroll
            for (int r = 0; r < 4; r++) acc[i][j][r] = 0.f;

    load_tiles(0, 0);
    CP_COMMIT();

    for (int it = 0; it < NIT; it++) {
        const int st = it & 1;
        if (it + 1 < NIT) {
            load_tiles((it + 1) & 1, (it + 1) * PBK);
            CP_COMMIT();
            CP_WAIT(1);
        } else {
            CP_WAIT(0);
        }
        __syncthreads();

        const float* A  = sA + st * PBM * SA_STR;
        const float* Bt = sB + st * PBK * SB_STR;
#pragma unroll
        for (int ks = 0; ks < 2; ks++) {
            const int kb = ks * 8;
            uint32_t af[2][4];
#pragma unroll
            for (int mt = 0; mt < 2; mt++) {
                const int row = wm * 32 + mt * 16 + g;
                af[mt][0] = f2tf32(A[row * SA_STR + kb + tig]);
                af[mt][1] = f2tf32(A[(row + 8) * SA_STR + kb + tig]);
                af[mt][2] = f2tf32(A[row * SA_STR + kb + tig + 4]);
                af[mt][3] = f2tf32(A[(row + 8) * SA_STR + kb + tig + 4]);
            }
#pragma unroll
            for (int nt = 0; nt < 12; nt++) {
                const int col = wn * 96 + nt * 8 + g;
                uint32_t bf[2];
                bf[0] = f2tf32(Bt[(kb + tig) * SB_STR + col]);
                bf[1] = f2tf32(Bt[(kb + tig + 4) * SB_STR + col]);
#pragma unroll
                for (int mt = 0; mt < 2; mt++)
                    mma_tf32(acc[mt][nt], af[mt], bf);
            }
        }
        __syncthreads();
    }

    // Epilogue: q/k normal layout; V transposed [b][h][s].
#pragma unroll
    for (int nt = 0; nt < 12; nt++) {
        const int col   = wn * 96 + nt * 8 + tig * 2;
        const int which = col >> 7;
        const int ocol  = col & 127;
#pragma unroll
        for (int mt = 0; mt < 2; mt++) {
            const int row = m0 + wm * 32 + mt * 16 + g;
            if (which == 2) {
                const int bidx = row >> 11;          // row / 2048
                const int s    = row & 2047;
                float* __restrict__ base = g_v + (size_t)bidx * HH * SS_;
                base[(size_t)ocol * SS_ + s]           = __uint_as_float(f2tf32(acc[mt][nt][0]));
                base[(size_t)(ocol + 1) * SS_ + s]     = __uint_as_float(f2tf32(acc[mt][nt][1]));
                base[(size_t)ocol * SS_ + s + 8]       = __uint_as_float(f2tf32(acc[mt][nt][2]));
                base[(size_t)(ocol + 1) * SS_ + s + 8] = __uint_as_float(f2tf32(acc[mt][nt][3]));
            } else {
                float* __restrict__ O = (which == 0) ? g_q : g_k;
                const float s = (which == 0) ? QSCALE : 1.f;
                float2 lo = make_float2(
                    __uint_as_float(f2tf32(acc[mt][nt][0] * s)),
                    __uint_as_float(f2tf32(acc[mt][nt][1] * s)));
                float2 hi = make_float2(
                    __uint_as_float(f2tf32(acc[mt][nt][2] * s)),
                    __uint_as_float(f2tf32(acc[mt][nt][3] * s)));
                *(float2*)(O + (size_t)row * HH + ocol)       = lo;
                *(float2*)(O + (size_t)(row + 8) * HH + ocol) = hi;
            }
        }
    }
}

// ---------------------------------------------------------------------------
// Flash attention (R12 pipeline + ldmatrix fragment loads).
// sK [key][h] stride 132; sVT [h][key] stride 68; sP [q][key] stride 68;
// all strides ≡ 4 mod 32 words -> LDSM 8-row groups are bank-conflict-free.
// ---------------------------------------------------------------------------
#define QSTR 132
#define KSTR 132
#define VTSTR 68
#define PSTR 68
#define ATT_SMEM ((32 * QSTR + 2 * 64 * KSTR + 2 * 128 * VTSTR + 32 * PSTR + 128) * 4)

__global__ __launch_bounds__(256, 1) void attn_tc_kernel(float* __restrict__ out)
{
    extern __shared__ __align__(16) uint32_t smA[];
    uint32_t* sQ  = smA;                        // 32*132
    uint32_t* sK  = sQ + 32 * QSTR;             // [2][64*132]
    uint32_t* sVT = sK + 2 * 64 * KSTR;         // [2][128*68]
    uint32_t* sP  = sVT + 2 * 128 * VTSTR;      // 32*68
    float* sRS = (float*)(sP + 32 * PSTR);      // 128

    const int b    = blockIdx.y;
    const int pr   = blockIdx.x;  // 0..31 -> q-tile pair (pr, 63-pr)
    const int tid  = threadIdx.x;
    const int wid  = tid >> 5;
    const int lane = tid & 31;
    const int g    = lane >> 2;
    const int tig  = lane & 3;
    const int wm   = wid >> 2;    // 0..1
    const int wn   = wid & 3;     // 0..3
    const int mi   = lane >> 3;   // ldmatrix matrix index
    const int r8   = lane & 7;    // ldmatrix row within matrix

    const float* __restrict__ qb = g_q + (size_t)b * SS_ * HH;
    const float* __restrict__ kb = g_k + (size_t)b * SS_ * HH;
    const float* __restrict__ vb = g_v + (size_t)b * HH * SS_;   // transposed

    // Per-lane LDSM byte offsets (within the respective tiles).
    const uint32_t koff = (uint32_t)(((wn * 16 + (mi >> 1) * 8 + r8) * KSTR
                                      + (mi & 1) * 4) * 4);
    const uint32_t qoff = (uint32_t)(((wm * 16 + (mi & 1) * 8 + r8) * QSTR
                                      + (mi >> 1) * 4) * 4);
    const uint32_t poff = (uint32_t)(((wm * 16 + (mi & 1) * 8 + r8) * PSTR
                                      + (mi >> 1) * 4) * 4);
    const uint32_t voff = (uint32_t)(((wn * 32 + (mi >> 1) * 8 + r8) * VTSTR
                                      + (mi & 1) * 4) * 4);

    const uint32_t sQ_b = smem_u32(sQ);
    const uint32_t sP_b = smem_u32(sP);

    auto issue_kv = [&](int st, int k0) {
        // K: 64 rows x 32 float4 = 2048 transfers (8*256).
#pragma unroll
        for (int p = 0; p < 8; p++) {
            int idx = p * 256 + tid;
            int row = idx >> 5, hq = idx & 31;
            CP_ASYNC16(smem_u32(&sK[st * 64 * KSTR + row * KSTR + hq * 4]),
                       kb + (size_t)(k0 + row) * HH + hq * 4);
            // V: 128 h-rows x 16 float4 (64 keys) = 2048 transfers (8*256).
            int h = idx >> 4, kq = idx & 15;
            CP_ASYNC16(smem_u32(&sVT[st * 128 * VTSTR + h * VTSTR + kq * 4]),
                       vb + (size_t)h * SS_ + k0 + kq * 4);
        }
    };

    for (int half = 0; half < 2; half++) {
        const int t  = (half == 0) ? pr : (63 - pr);
        const int q0 = t * 32;
        const int nkt = t / 2 + 1;

        __syncthreads();  // prev half fully done with all smem

        // Issue Q + first K/V tile as one group.
#pragma unroll
        for (int p = 0; p < 4; p++) {
            int idx = p * 256 + tid;
            int row = idx >> 5, hq = idx & 31;
            CP_ASYNC16(smem_u32(&sQ[row * QSTR + hq * 4]),
                       qb + (size_t)(q0 + row) * HH + hq * 4);
        }
        issue_kv(0, 0);
        CP_COMMIT();

        uint32_t aq[16][4];

        float l0 = 0.f, l1 = 0.f;
        float acc[4][4];
#pragma unroll
        for (int nt = 0; nt < 4; nt++)
#pragma unroll
            for (int r = 0; r < 4; r++) acc[nt][r] = 0.f;

        const int row0 = q0 + wm * 16 + g;

        for (int kt = 0; kt < nkt; kt++) {
            const int buf = kt & 1;
            if (kt + 1 < nkt) {
                issue_kv((kt + 1) & 1, (kt + 1) * 64);
                CP_COMMIT();
                CP_WAIT(1);
            } else {
                CP_WAIT(0);
            }
            __syncthreads();

            if (kt == 0) {
#pragma unroll
                for (int ks = 0; ks < 16; ks++)
                    ldsm_x4(aq[ks][0], aq[ks][1], aq[ks][2], aq[ks][3],
                            sQ_b + qoff + ks * 32);
            }

            const uint32_t sKb = smem_u32(sK + buf * 64 * KSTR);
            const uint32_t sVb = smem_u32(sVT + buf * 128 * VTSTR);
            const int k0 = kt * 64;

            // ---- S = Q K^T : per ks, 2 LDSM.x4 feed 4 MMA chains ----
            float sf[2][4], sg[2][4];
#pragma unroll
            for (int nt = 0; nt < 2; nt++)
#pragma unroll
                for (int r = 0; r < 4; r++) { sf[nt][r] = 0.f; sg[nt][r] = 0.f; }
#pragma unroll
            for (int ks = 0; ks < 8; ks++) {
                uint32_t kA[4], kB[4];
                ldsm_x4(kA[0], kA[1], kA[2], kA[3], sKb + koff + ks * 32);
                ldsm_x4(kB[0], kB[1], kB[2], kB[3], sKb + koff + (ks + 8) * 32);
                mma_tf32(sf[0], aq[ks], kA);          // nt0: {klo,khi}
                mma_tf32(sf[1], aq[ks], kA + 2);      // nt1
                mma_tf32(sg[0], aq[ks + 8], kB);
                mma_tf32(sg[1], aq[ks + 8], kB + 2);
            }

            // ---- exp (no max shift) + causal mask + P store + l partials ----
#pragma unroll
            for (int nt = 0; nt < 2; nt++) {
#pragma unroll
                for (int j = 0; j < 2; j++) {
                    const int c   = wn * 16 + nt * 8 + tig * 2 + j;
                    const int col = k0 + c;
                    float s0 = sf[nt][j]     + sg[nt][j];
                    float s1 = sf[nt][j + 2] + sg[nt][j + 2];
                    float p0 = (col <= row0)     ? __expf(s0) : 0.f;
                    float p1 = (col <= row0 + 8) ? __expf(s1) : 0.f;
                    l0 += p0; l1 += p1;
                    sP[(wm * 16 + g) * PSTR + c]     = f2tf32(p0);
                    sP[(wm * 16 + g + 8) * PSTR + c] = f2tf32(p1);
                }
            }
            BAR_SYNC(1 + wm, 128);   // P visible within the wm row-group

            // ---- O += P V : per ks, 3 LDSM.x4 feed 4 MMAs ----
#pragma unroll
            for (int ks = 0; ks < 8; ks++) {
                uint32_t ap[4], v0[4], v1[4];
                ldsm_x4(ap[0], ap[1], ap[2], ap[3], sP_b + poff + ks * 32);
                ldsm_x4(v0[0], v0[1], v0[2], v0[3], sVb + voff + ks * 32);
                ldsm_x4(v1[0], v1[1], v1[2], v1[3],
                        sVb + voff + 16 * VTSTR * 4 + ks * 32);
                mma_tf32(acc[0], ap, v0);        // nt0
                mma_tf32(acc[1], ap, v0 + 2);    // nt1
                mma_tf32(acc[2], ap, v1);        // nt2
                mma_tf32(acc[3], ap, v1 + 2);    // nt3
            }
            __syncthreads();  // all reads of this buf done before next issue
        }

        // ---- l reduction: quad shfl -> cross-wn via smem (once per tile) ----
#pragma unroll
        for (int off = 1; off <= 2; off <<= 1) {
            l0 += __shfl_xor_sync(0xffffffffu, l0, off);
            l1 += __shfl_xor_sync(0xffffffffu, l1, off);
        }
        if (tig == 0) {
            sRS[wn * 32 + wm * 16 + g]     = l0;
            sRS[wn * 32 + wm * 16 + g + 8] = l1;
        }
        __syncthreads();
        float ts0 = sRS[wm * 16 + g], ts1 = sRS[wm * 16 + g + 8];
#pragma unroll
        for (int w = 1; w < 4; w++) {
            ts0 += sRS[w * 32 + wm * 16 + g];
            ts1 += sRS[w * 32 + wm * 16 + g + 8];
        }

        // ---- epilogue ----
        const float inv0 = 1.f / ts0;
        const float inv1 = 1.f / ts1;
#pragma unroll
        for (int nt = 0; nt < 4; nt++) {
            const int col = wn * 32 + nt * 8 + tig * 2;
            *(float2*)(out + ((size_t)b * SS_ + row0) * HH + col) =
                make_float2(acc[nt][0] * inv0, acc[nt][1] * inv0);
            *(float2*)(out + ((size_t)b * SS_ + row0 + 8) * HH + col) =
                make_float2(acc[nt][2] * inv1, acc[nt][3] * inv1);
        }
    }
}

// ---------------------------------------------------------------------------
extern "C" void kernel_launch(void* const* d_in, const int* in_sizes, int n_in,
                              void* d_out, int out_size)
{
    const float* x  = (const float*)d_in[0];
    const float* Wq = (const float*)d_in[1];
    const float* Wk = (const float*)d_in[2];
    const float* Wv = (const float*)d_in[3];
    float* out = (float*)d_out;

    cudaFuncSetAttribute(proj_mma_kernel, cudaFuncAttributeMaxDynamicSharedMemorySize,
                         PROJ_SMEM);
    cudaFuncSetAttribute(attn_tc_kernel, cudaFuncAttributeMaxDynamicSharedMemorySize,
                         ATT_SMEM);

    proj_mma_kernel<<<8192 / PBM, 256, PROJ_SMEM>>>(x, Wq, Wk, Wv);
    attn_tc_kernel<<<dim3(32, 4), 256, ATT_SMEM>>>(out);
}

// round 16
// speedup vs baseline: 1.5832x; 1.5832x over previous
#include <cuda_runtime.h>
#include <cstdint>

#define BB 4
#define SS_ 2048
#define EE 1024
#define HH 128

#define NEG_INF (-1e30f)
#define QSCALE 0.08838834764831845f   // 1/sqrt(128)

// Scratch for projected q/k/v (device globals: no allocation allowed).
// Stored PRE-ROUNDED to tf32 (and g_q pre-scaled by 1/sqrt(128)).
__device__ float g_q[BB * SS_ * HH];
__device__ float g_k[BB * SS_ * HH];
__device__ float g_v[BB * SS_ * HH];

// ---------------------------------------------------------------------------
// Helpers
// ---------------------------------------------------------------------------
__device__ __forceinline__ uint32_t smem_u32(const void* p) {
    uint32_t a;
    asm("{ .reg .u64 t; cvta.to.shared.u64 t, %1; cvt.u32.u64 %0, t; }"
        : "=r"(a) : "l"(p));
    return a;
}
__device__ __forceinline__ uint32_t f2tf32(float f) {
    uint32_t r;
    asm("cvt.rna.tf32.f32 %0, %1;" : "=r"(r) : "f"(f));
    return r;
}
__device__ __forceinline__ void mma_tf32(float* d, const uint32_t* a,
                                         const uint32_t* b) {
    asm volatile(
        "mma.sync.aligned.m16n8k8.row.col.f32.tf32.tf32.f32 "
        "{%0,%1,%2,%3}, {%4,%5,%6,%7}, {%8,%9}, {%0,%1,%2,%3};"
        : "+f"(d[0]), "+f"(d[1]), "+f"(d[2]), "+f"(d[3])
        : "r"(a[0]), "r"(a[1]), "r"(a[2]), "r"(a[3]), "r"(b[0]), "r"(b[1]));
}
#define CP_ASYNC16(dst_u32, src) \
    asm volatile("cp.async.cg.shared.global [%0], [%1], 16;" :: "r"(dst_u32), "l"(src))
#define CP_COMMIT() asm volatile("cp.async.commit_group;" ::: "memory")
#define CP_WAIT(n)  asm volatile("cp.async.wait_group %0;" :: "n"(n) : "memory")
#define BAR_SYNC(id, n) asm volatile("bar.sync %0, %1;" :: "r"(id), "r"(n) : "memory")

// ---------------------------------------------------------------------------
// Fused projection GEMM (R12, unchanged): O[M,384] = X[M,E] @ [Wq|Wk|Wv].
// ---------------------------------------------------------------------------
#define PBM 64
#define PBK 16
#define SA_STR 20
#define SB_STR 392
#define PROJ_SMEM ((2 * PBM * SA_STR + 2 * PBK * SB_STR) * 4)  // 60416 B
#define NIT (EE / PBK)   // 64

__global__ __launch_bounds__(256, 1) void proj_mma_kernel(
    const float* __restrict__ x,
    const float* __restrict__ Wq,
    const float* __restrict__ Wk,
    const float* __restrict__ Wv)
{
    extern __shared__ float psm[];
    float* sA = psm;                        // [2][64*20]
    float* sB = psm + 2 * PBM * SA_STR;     // [2][16*392]

    const int m0   = blockIdx.x * PBM;
    const int tid  = threadIdx.x;
    const int wid  = tid >> 5;
    const int lane = tid & 31;
    const int g    = lane >> 2;
    const int tig  = lane & 3;
    const int wm   = wid & 1;
    const int wn   = wid >> 1;

    const float* __restrict__ Ws[3] = {Wq, Wk, Wv};

    auto load_tiles = [&](int st, int k0) {
        {
            int r = tid >> 2, qa = tid & 3;
            CP_ASYNC16(smem_u32(&sA[st * PBM * SA_STR + r * SA_STR + qa * 4]),
                       x + (size_t)(m0 + r) * EE + k0 + qa * 4);
        }
#pragma unroll
        for (int p = 0; p < 6; p++) {
            int idx = p * 256 + tid;
            int row = idx / 96, q = idx % 96;
            int col4 = q * 4;
            const float* W = Ws[col4 >> 7];
            int wcol = col4 & 127;
            CP_ASYNC16(smem_u32(&sB[st * PBK * SB_STR + row * SB_STR + col4]),
                       W + (size_t)(k0 + row) * HH + wcol);
        }
    };

    float acc[2][12][4];
#pragma unroll
    for (int i = 0; i < 2; i++)
#pragma unroll
        for (int j = 0; j < 12; j++)
#pragma unroll
            for (int r = 0; r < 4; r++) acc[i][j][r] = 0.f;

    load_tiles(0, 0);
    CP_COMMIT();

    for (int it = 0; it < NIT; it++) {
        const int st = it & 1;
        if (it + 1 < NIT) {
            load_tiles((it + 1) & 1, (it + 1) * PBK);
            CP_COMMIT();
            CP_WAIT(1);
        } else {
            CP_WAIT(0);
        }
        __syncthreads();

        const float* A  = sA + st * PBM * SA_STR;
        const float* Bt = sB + st * PBK * SB_STR;
#pragma unroll
        for (int ks = 0; ks < 2; ks++) {
            const int kb = ks * 8;
            uint32_t af[2][4];
#pragma unroll
            for (int mt = 0; mt < 2; mt++) {
                const int row = wm * 32 + mt * 16 + g;
                af[mt][0] = f2tf32(A[row * SA_STR + kb + tig]);
                af[mt][1] = f2tf32(A[(row + 8) * SA_STR + kb + tig]);
                af[mt][2] = f2tf32(A[row * SA_STR + kb + tig + 4]);
                af[mt][3] = f2tf32(A[(row + 8) * SA_STR + kb + tig + 4]);
            }
#pragma unroll
            for (int nt = 0; nt < 12; nt++) {
                const int col = wn * 96 + nt * 8 + g;
                uint32_t bf[2];
                bf[0] = f2tf32(Bt[(kb + tig) * SB_STR + col]);
                bf[1] = f2tf32(Bt[(kb + tig + 4) * SB_STR + col]);
#pragma unroll
                for (int mt = 0; mt < 2; mt++)
                    mma_tf32(acc[mt][nt], af[mt], bf);
            }
        }
        __syncthreads();
    }

#pragma unroll
    for (int nt = 0; nt < 12; nt++) {
        const int col   = wn * 96 + nt * 8 + tig * 2;
        const int which = col >> 7;
        const int ocol  = col & 127;
        float* __restrict__ O = (which == 0) ? g_q : (which == 1) ? g_k : g_v;
        const float s = (which == 0) ? QSCALE : 1.f;
#pragma unroll
        for (int mt = 0; mt < 2; mt++) {
            const int row = m0 + wm * 32 + mt * 16 + g;
            float2 lo = make_float2(
                __uint_as_float(f2tf32(acc[mt][nt][0] * s)),
                __uint_as_float(f2tf32(acc[mt][nt][1] * s)));
            float2 hi = make_float2(
                __uint_as_float(f2tf32(acc[mt][nt][2] * s)),
                __uint_as_float(f2tf32(acc[mt][nt][3] * s)));
            *(float2*)(O + (size_t)row * HH + ocol)       = lo;
            *(float2*)(O + (size_t)(row + 8) * HH + ocol) = hi;
        }
    }
}

// ---------------------------------------------------------------------------
// Flash attention, tf32 mma — R12 pipeline with 512 threads (16 warps).
// Warp (wm 0..1, wn 0..7).  S: rows wm*16+16, cols wn*8+8 (1 nt x 16 ks).
// PV: rows wm*16+16, h-cols wn*16+16 (2 nt x 8 ks).  Double-buffered K/V,
// issue-before-compute + CP_WAIT(1).  No-max softmax, deferred l reduce.
// ---------------------------------------------------------------------------
#define QSTR 132
#define KSTR 132
#define VSTR 136
#define PSTR 68
#define ATT_SMEM ((32 * QSTR + 2 * 64 * KSTR + 2 * 64 * VSTR + 32 * PSTR + 256) * 4)

__global__ __launch_bounds__(512, 1) void attn_tc_kernel(float* __restrict__ out)
{
    extern __shared__ uint32_t smA[];
    uint32_t* sQ = smA;                        // 32*132
    uint32_t* sK = sQ + 32 * QSTR;             // [2][64*132]
    uint32_t* sV = sK + 2 * 64 * KSTR;         // [2][64*136]
    uint32_t* sP = sV + 2 * 64 * VSTR;         // 32*68
    float* sRS = (float*)(sP + 32 * PSTR);     // 256

    const int b    = blockIdx.y;
    const int pr   = blockIdx.x;  // 0..31 -> q-tile pair (pr, 63-pr)
    const int tid  = threadIdx.x;
    const int wid  = tid >> 5;
    const int lane = tid & 31;
    const int g    = lane >> 2;
    const int tig  = lane & 3;
    const int wm   = wid >> 3;    // 0..1
    const int wn   = wid & 7;     // 0..7

    const float* __restrict__ qb = g_q + (size_t)b * SS_ * HH;
    const float* __restrict__ kb = g_k + (size_t)b * SS_ * HH;
    const float* __restrict__ vb = g_v + (size_t)b * SS_ * HH;

    auto issue_kv = [&](int st, int k0) {
        // K,V tiles 64 rows x 32 float4 each = 2048 transfers = 4*512.
#pragma unroll
        for (int p = 0; p < 4; p++) {
            int idx = p * 512 + tid;
            int row = idx >> 5, hq = idx & 31;
            CP_ASYNC16(smem_u32(&sK[st * 64 * KSTR + row * KSTR + hq * 4]),
                       kb + (size_t)(k0 + row) * HH + hq * 4);
            CP_ASYNC16(smem_u32(&sV[st * 64 * VSTR + row * VSTR + hq * 4]),
                       vb + (size_t)(k0 + row) * HH + hq * 4);
        }
    };

    for (int half = 0; half < 2; half++) {
        const int t  = (half == 0) ? pr : (63 - pr);
        const int q0 = t * 32;
        const int nkt = t / 2 + 1;

        __syncthreads();  // prev half fully done with all smem

        // Issue Q + first K/V tile as one group.  Q: 1024 transfers = 2*512.
#pragma unroll
        for (int p = 0; p < 2; p++) {
            int idx = p * 512 + tid;
            int row = idx >> 5, hq = idx & 31;
            CP_ASYNC16(smem_u32(&sQ[row * QSTR + hq * 4]),
                       qb + (size_t)(q0 + row) * HH + hq * 4);
        }
        issue_kv(0, 0);
        CP_COMMIT();

        uint32_t aq[16][4];
        const int qrow = wm * 16 + g;

        float l0 = 0.f, l1 = 0.f;
        float acc[2][4];
#pragma unroll
        for (int nt = 0; nt < 2; nt++)
#pragma unroll
            for (int r = 0; r < 4; r++) acc[nt][r] = 0.f;

        const int row0 = q0 + qrow;

        for (int kt = 0; kt < nkt; kt++) {
            const int buf = kt & 1;
            if (kt + 1 < nkt) {
                issue_kv((kt + 1) & 1, (kt + 1) * 64);
                CP_COMMIT();
                CP_WAIT(1);
            } else {
                CP_WAIT(0);
            }
            __syncthreads();

            if (kt == 0) {
#pragma unroll
                for (int ks = 0; ks < 16; ks++) {
                    aq[ks][0] = sQ[qrow * QSTR + ks * 8 + tig];
                    aq[ks][1] = sQ[(qrow + 8) * QSTR + ks * 8 + tig];
                    aq[ks][2] = sQ[qrow * QSTR + ks * 8 + tig + 4];
                    aq[ks][3] = sQ[(qrow + 8) * QSTR + ks * 8 + tig + 4];
                }
            }

            const uint32_t* Kb = sK + buf * 64 * KSTR;
            const uint32_t* Vb = sV + buf * 64 * VSTR;
            const int k0 = kt * 64;

            // ---- S = Q K^T : 1 n-tile, k split in halves -> 2 chains ----
            float sf[4], sg[4];
#pragma unroll
            for (int r = 0; r < 4; r++) { sf[r] = 0.f; sg[r] = 0.f; }
            const int ncolS = wn * 8 + g;
#pragma unroll
            for (int ks = 0; ks < 8; ks++) {
                uint32_t bfA[2], bfB[2];
                bfA[0] = Kb[ncolS * KSTR + ks * 8 + tig];
                bfA[1] = Kb[ncolS * KSTR + ks * 8 + tig + 4];
                bfB[0] = Kb[ncolS * KSTR + (ks + 8) * 8 + tig];
                bfB[1] = Kb[ncolS * KSTR + (ks + 8) * 8 + tig + 4];
                mma_tf32(sf, aq[ks], bfA);
                mma_tf32(sg, aq[ks + 8], bfB);
            }

            // ---- exp (no max shift) + causal mask + P store + l partials ----
#pragma unroll
            for (int j = 0; j < 2; j++) {
                const int c   = wn * 8 + tig * 2 + j;
                const int col = k0 + c;
                float s0 = sf[j]     + sg[j];
                float s1 = sf[j + 2] + sg[j + 2];
                float p0 = (col <= row0)     ? __expf(s0) : 0.f;
                float p1 = (col <= row0 + 8) ? __expf(s1) : 0.f;
                l0 += p0; l1 += p1;
                sP[(wm * 16 + g) * PSTR + c]     = f2tf32(p0);
                sP[(wm * 16 + g + 8) * PSTR + c] = f2tf32(p1);
            }
            BAR_SYNC(1 + wm, 256);   // P visible within the wm row-group

            // ---- O += P V : 2 n-tiles x 8 k-steps ----
#pragma unroll
            for (int ks = 0; ks < 8; ks++) {
                uint32_t ap[4];
                ap[0] = sP[(wm * 16 + g) * PSTR + ks * 8 + tig];
                ap[1] = sP[(wm * 16 + g + 8) * PSTR + ks * 8 + tig];
                ap[2] = sP[(wm * 16 + g) * PSTR + ks * 8 + tig + 4];
                ap[3] = sP[(wm * 16 + g + 8) * PSTR + ks * 8 + tig + 4];
#pragma unroll
                for (int nt = 0; nt < 2; nt++) {
                    const int ncol = wn * 16 + nt * 8 + g;
                    uint32_t bf[2];
                    bf[0] = Vb[(ks * 8 + tig) * VSTR + ncol];
                    bf[1] = Vb[(ks * 8 + tig + 4) * VSTR + ncol];
                    mma_tf32(acc[nt], ap, bf);
                }
            }
            __syncthreads();  // all reads of this buf done before next issue
        }

        // ---- l reduction: quad shfl -> cross-wn via smem (once per tile) ----
#pragma unroll
        for (int off = 1; off <= 2; off <<= 1) {
            l0 += __shfl_xor_sync(0xffffffffu, l0, off);
            l1 += __shfl_xor_sync(0xffffffffu, l1, off);
        }
        if (tig == 0) {
            sRS[wn * 32 + wm * 16 + g]     = l0;
            sRS[wn * 32 + wm * 16 + g + 8] = l1;
        }
        __syncthreads();
        float ts0 = sRS[wm * 16 + g], ts1 = sRS[wm * 16 + g + 8];
#pragma unroll
        for (int w = 1; w < 8; w++) {
            ts0 += sRS[w * 32 + wm * 16 + g];
            ts1 += sRS[w * 32 + wm * 16 + g + 8];
        }

        // ---- epilogue ----
        const float inv0 = 1.f / ts0;
        const float inv1 = 1.f / ts1;
#pragma unroll
        for (int nt = 0; nt < 2; nt++) {
            const int col = wn * 16 + nt * 8 + tig * 2;
            *(float2*)(out + ((size_t)b * SS_ + row0) * HH + col) =
                make_float2(acc[nt][0] * inv0, acc[nt][1] * inv0);
            *(float2*)(out + ((size_t)b * SS_ + row0 + 8) * HH + col) =
                make_float2(acc[nt][2] * inv1, acc[nt][3] * inv1);
        }
    }
}

// ---------------------------------------------------------------------------
extern "C" void kernel_launch(void* const* d_in, const int* in_sizes, int n_in,
                              void* d_out, int out_size)
{
    const float* x  = (const float*)d_in[0];
    const float* Wq = (const float*)d_in[1];
    const float* Wk = (const float*)d_in[2];
    const float* Wv = (const float*)d_in[3];
    float* out = (float*)d_out;

    cudaFuncSetAttribute(proj_mma_kernel, cudaFuncAttributeMaxDynamicSharedMemorySize,
                         PROJ_SMEM);
    cudaFuncSetAttribute(attn_tc_kernel, cudaFuncAttributeMaxDynamicSharedMemorySize,
                         ATT_SMEM);

    proj_mma_kernel<<<8192 / PBM, 256, PROJ_SMEM>>>(x, Wq, Wk, Wv);
    attn_tc_kernel<<<dim3(32, 4), 512, ATT_SMEM>>>(out);
}

// round 17
// speedup vs baseline: 1.6777x; 1.0597x over previous
#include <cuda_runtime.h>
#include <cstdint>

#define BB 4
#define SS_ 2048
#define EE 1024
#define HH 128

#define QSCALE 0.08838834764831845f   // 1/sqrt(128)

// Scratch for projected q/k/v (device globals: no allocation allowed).
// Stored PRE-ROUNDED to tf32 (and g_q pre-scaled by 1/sqrt(128)).
__device__ float g_q[BB * SS_ * HH];
__device__ float g_k[BB * SS_ * HH];
__device__ float g_v[BB * SS_ * HH];

// ---------------------------------------------------------------------------
// Helpers
// ---------------------------------------------------------------------------
__device__ __forceinline__ uint32_t smem_u32(const void* p) {
    uint32_t a;
    asm("{ .reg .u64 t; cvta.to.shared.u64 t, %1; cvt.u32.u64 %0, t; }"
        : "=r"(a) : "l"(p));
    return a;
}
__device__ __forceinline__ uint32_t f2tf32(float f) {
    uint32_t r;
    asm("cvt.rna.tf32.f32 %0, %1;" : "=r"(r) : "f"(f));
    return r;
}
__device__ __forceinline__ void mma_tf32(float* d, const uint32_t* a,
                                         const uint32_t* b) {
    asm volatile(
        "mma.sync.aligned.m16n8k8.row.col.f32.tf32.tf32.f32 "
        "{%0,%1,%2,%3}, {%4,%5,%6,%7}, {%8,%9}, {%0,%1,%2,%3};"
        : "+f"(d[0]), "+f"(d[1]), "+f"(d[2]), "+f"(d[3])
        : "r"(a[0]), "r"(a[1]), "r"(a[2]), "r"(a[3]), "r"(b[0]), "r"(b[1]));
}
#define CP_ASYNC16(dst_u32, src) \
    asm volatile("cp.async.cg.shared.global [%0], [%1], 16;" :: "r"(dst_u32), "l"(src))
#define CP_COMMIT() asm volatile("cp.async.commit_group;" ::: "memory")
#define CP_WAIT(n)  asm volatile("cp.async.wait_group %0;" :: "n"(n) : "memory")

// ---------------------------------------------------------------------------
// Fused projection GEMM (R12, unchanged): O[M,384] = X[M,E] @ [Wq|Wk|Wv].
// ---------------------------------------------------------------------------
#define PBM 64
#define PBK 16
#define SA_STR 20
#define SB_STR 392
#define PROJ_SMEM ((2 * PBM * SA_STR + 2 * PBK * SB_STR) * 4)  // 60416 B
#define NIT (EE / PBK)   // 64

__global__ __launch_bounds__(256, 1) void proj_mma_kernel(
    const float* __restrict__ x,
    const float* __restrict__ Wq,
    const float* __restrict__ Wk,
    const float* __restrict__ Wv)
{
    extern __shared__ float psm[];
    float* sA = psm;                        // [2][64*20]
    float* sB = psm + 2 * PBM * SA_STR;     // [2][16*392]

    const int m0   = blockIdx.x * PBM;
    const int tid  = threadIdx.x;
    const int wid  = tid >> 5;
    const int lane = tid & 31;
    const int g    = lane >> 2;
    const int tig  = lane & 3;
    const int wm   = wid & 1;
    const int wn   = wid >> 1;

    const float* __restrict__ Ws[3] = {Wq, Wk, Wv};

    auto load_tiles = [&](int st, int k0) {
        {
            int r = tid >> 2, qa = tid & 3;
            CP_ASYNC16(smem_u32(&sA[st * PBM * SA_STR + r * SA_STR + qa * 4]),
                       x + (size_t)(m0 + r) * EE + k0 + qa * 4);
        }
#pragma unroll
        for (int p = 0; p < 6; p++) {
            int idx = p * 256 + tid;
            int row = idx / 96, q = idx % 96;
            int col4 = q * 4;
            const float* W = Ws[col4 >> 7];
            int wcol = col4 & 127;
            CP_ASYNC16(smem_u32(&sB[st * PBK * SB_STR + row * SB_STR + col4]),
                       W + (size_t)(k0 + row) * HH + wcol);
        }
    };

    float acc[2][12][4];
#pragma unroll
    for (int i = 0; i < 2; i++)
#pragma unroll
        for (int j = 0; j < 12; j++)
#pragma unroll
            for (int r = 0; r < 4; r++) acc[i][j][r] = 0.f;

    load_tiles(0, 0);
    CP_COMMIT();

    for (int it = 0; it < NIT; it++) {
        const int st = it & 1;
        if (it + 1 < NIT) {
            load_tiles((it + 1) & 1, (it + 1) * PBK);
            CP_COMMIT();
            CP_WAIT(1);
        } else {
            CP_WAIT(0);
        }
        __syncthreads();

        const float* A  = sA + st * PBM * SA_STR;
        const float* Bt = sB + st * PBK * SB_STR;
#pragma unroll
        for (int ks = 0; ks < 2; ks++) {
            const int kb = ks * 8;
            uint32_t af[2][4];
#pragma unroll
            for (int mt = 0; mt < 2; mt++) {
                const int row = wm * 32 + mt * 16 + g;
                af[mt][0] = f2tf32(A[row * SA_STR + kb + tig]);
                af[mt][1] = f2tf32(A[(row + 8) * SA_STR + kb + tig]);
                af[mt][2] = f2tf32(A[row * SA_STR + kb + tig + 4]);
                af[mt][3] = f2tf32(A[(row + 8) * SA_STR + kb + tig + 4]);
            }
#pragma unroll
            for (int nt = 0; nt < 12; nt++) {
                const int col = wn * 96 + nt * 8 + g;
                uint32_t bf[2];
                bf[0] = f2tf32(Bt[(kb + tig) * SB_STR + col]);
                bf[1] = f2tf32(Bt[(kb + tig + 4) * SB_STR + col]);
#pragma unroll
                for (int mt = 0; mt < 2; mt++)
                    mma_tf32(acc[mt][nt], af[mt], bf);
            }
        }
        __syncthreads();
    }

#pragma unroll
    for (int nt = 0; nt < 12; nt++) {
        const int col   = wn * 96 + nt * 8 + tig * 2;
        const int which = col >> 7;
        const int ocol  = col & 127;
        float* __restrict__ O = (which == 0) ? g_q : (which == 1) ? g_k : g_v;
        const float s = (which == 0) ? QSCALE : 1.f;
#pragma unroll
        for (int mt = 0; mt < 2; mt++) {
            const int row = m0 + wm * 32 + mt * 16 + g;
            float2 lo = make_float2(
                __uint_as_float(f2tf32(acc[mt][nt][0] * s)),
                __uint_as_float(f2tf32(acc[mt][nt][1] * s)));
            float2 hi = make_float2(
                __uint_as_float(f2tf32(acc[mt][nt][2] * s)),
                __uint_as_float(f2tf32(acc[mt][nt][3] * s)));
            *(float2*)(O + (size_t)row * HH + ocol)       = lo;
            *(float2*)(O + (size_t)(row + 8) * HH + ocol) = hi;
        }
    }
}

// ---------------------------------------------------------------------------
// Flash attention, tf32 mma — split-K PV with register-resident P.
// 256 thr, warp (wm 0..1, wn 0..3).  Warp owns 16 keys (cols wn*16..+15).
// S: 2 nt x 16 ks (as R12).  P stays in regs (quad-shuffle D->A fragment
// conversion).  PV: warp accumulates O[16 rows][128 h] over ITS 16 keys
// (16 nt x 2 chunks); cross-wn sum once per q-tile via smem staging.
// Per step: CP_WAIT + 1 syncthreads ONLY (no named barrier, no P smem).
// ---------------------------------------------------------------------------
#define QSTR 132
#define KSTR 132
#define VSTR 136
#define RSTR 132
#define N_STAGE (6 * 16 * RSTR)   // 3 slots x 16 rows x RSTR per wm group
#define ATT_SMEM ((32 * QSTR + 2 * 64 * KSTR + 2 * 64 * VSTR + N_STAGE + 128) * 4)

__global__ __launch_bounds__(256, 1) void attn_tc_kernel(float* __restrict__ out)
{
    extern __shared__ uint32_t smA[];
    uint32_t* sQ = smA;                        // 32*132
    uint32_t* sK = sQ + 32 * QSTR;             // [2][64*132]
    uint32_t* sV = sK + 2 * 64 * KSTR;         // [2][64*136]
    float* sStage = (float*)(sV + 2 * 64 * VSTR);  // [2 wm][3 slots][16*132]
    float* sRS = sStage + N_STAGE;             // 128

    const int b    = blockIdx.y;
    const int pr   = blockIdx.x;  // 0..31 -> q-tile pair (pr, 63-pr)
    const int tid  = threadIdx.x;
    const int wid  = tid >> 5;
    const int lane = tid & 31;
    const int g    = lane >> 2;
    const int tig  = lane & 3;
    const int wm   = wid >> 2;    // 0..1
    const int wn   = wid & 3;     // 0..3

    const float* __restrict__ qb = g_q + (size_t)b * SS_ * HH;
    const float* __restrict__ kb = g_k + (size_t)b * SS_ * HH;
    const float* __restrict__ vb = g_v + (size_t)b * SS_ * HH;

    // Shuffle sources for D->A fragment conversion (within-warp lanes).
    const int srcA = g * 4 + (tig >> 1);
    const int srcB = srcA + 2;
    const bool selOdd = (tig & 1);

    auto issue_kv = [&](int st, int k0) {
        // K,V tiles 64 rows x 32 float4 each = 2048 transfers (8*256).
#pragma unroll
        for (int p = 0; p < 8; p++) {
            int idx = p * 256 + tid;
            int row = idx >> 5, hq = idx & 31;
            CP_ASYNC16(smem_u32(&sK[st * 64 * KSTR + row * KSTR + hq * 4]),
                       kb + (size_t)(k0 + row) * HH + hq * 4);
            CP_ASYNC16(smem_u32(&sV[st * 64 * VSTR + row * VSTR + hq * 4]),
                       vb + (size_t)(k0 + row) * HH + hq * 4);
        }
    };

    for (int half = 0; half < 2; half++) {
        const int t  = (half == 0) ? pr : (63 - pr);
        const int q0 = t * 32;
        const int nkt = t / 2 + 1;

        __syncthreads();  // prev half fully done with all smem

        // Prologue: issue Q + K/V(0) as one group.
#pragma unroll
        for (int p = 0; p < 4; p++) {
            int idx = p * 256 + tid;
            int row = idx >> 5, hq = idx & 31;
            CP_ASYNC16(smem_u32(&sQ[row * QSTR + hq * 4]),
                       qb + (size_t)(q0 + row) * HH + hq * 4);
        }
        issue_kv(0, 0);
        CP_COMMIT();

        uint32_t aq[16][4];
        const int qrow = wm * 16 + g;
        const int row0 = q0 + qrow;

        float l0 = 0.f, l1 = 0.f;
        float acc[16][4];
#pragma unroll
        for (int nt = 0; nt < 16; nt++)
#pragma unroll
            for (int r = 0; r < 4; r++) acc[nt][r] = 0.f;

        for (int kt = 0; kt < nkt; kt++) {
            const int buf = kt & 1;
            CP_WAIT(0);
            __syncthreads();   // K/V(kt) visible; all warps done with buf kt-1

            // Issue next tile AFTER the sync: target buffer is free (its last
            // readers were step kt-1, all past the sync above).
            if (kt + 1 < nkt) {
                issue_kv((kt + 1) & 1, (kt + 1) * 64);
                CP_COMMIT();
            }

            if (kt == 0) {
#pragma unroll
                for (int ks = 0; ks < 16; ks++) {
                    aq[ks][0] = sQ[qrow * QSTR + ks * 8 + tig];
                    aq[ks][1] = sQ[(qrow + 8) * QSTR + ks * 8 + tig];
                    aq[ks][2] = sQ[qrow * QSTR + ks * 8 + tig + 4];
                    aq[ks][3] = sQ[(qrow + 8) * QSTR + ks * 8 + tig + 4];
                }
            }

            const uint32_t* Kb = sK + buf * 64 * KSTR;
            const uint32_t* Vb = sV + buf * 64 * VSTR;
            const int k0 = kt * 64;

            // ---- S = Q K^T : 2 n-tiles (the warp's 16 keys), 4 chains ----
            float sf[2][4], sg[2][4];
#pragma unroll
            for (int nt = 0; nt < 2; nt++)
#pragma unroll
                for (int r = 0; r < 4; r++) { sf[nt][r] = 0.f; sg[nt][r] = 0.f; }
#pragma unroll
            for (int ks = 0; ks < 8; ks++) {
#pragma unroll
                for (int nt = 0; nt < 2; nt++) {
                    const int ncol = wn * 16 + nt * 8 + g;
                    uint32_t bfA[2], bfB[2];
                    bfA[0] = Kb[ncol * KSTR + ks * 8 + tig];
                    bfA[1] = Kb[ncol * KSTR + ks * 8 + tig + 4];
                    bfB[0] = Kb[ncol * KSTR + (ks + 8) * 8 + tig];
                    bfB[1] = Kb[ncol * KSTR + (ks + 8) * 8 + tig + 4];
                    mma_tf32(sf[nt], aq[ks], bfA);
                    mma_tf32(sg[nt], aq[ks + 8], bfB);
                }
            }

            // ---- exp (no max shift) + causal mask -> P in registers ----
            uint32_t pv[2][4];
#pragma unroll
            for (int nt = 0; nt < 2; nt++) {
#pragma unroll
                for (int j = 0; j < 2; j++) {
                    const int col = k0 + wn * 16 + nt * 8 + tig * 2 + j;
                    float s0 = sf[nt][j]     + sg[nt][j];
                    float s1 = sf[nt][j + 2] + sg[nt][j + 2];
                    float p0 = (col <= row0)     ? __expf(s0) : 0.f;
                    float p1 = (col <= row0 + 8) ? __expf(s1) : 0.f;
                    l0 += p0; l1 += p1;
                    pv[nt][j]     = f2tf32(p0);
                    pv[nt][j + 2] = f2tf32(p1);
                }
            }

            // ---- O += P V : split-K over warps; P via quad-shuffles ----
#pragma unroll
            for (int c = 0; c < 2; c++) {
                uint32_t pa[4];
                uint32_t u0 = __shfl_sync(0xffffffffu, pv[c][0], srcA);
                uint32_t u1 = __shfl_sync(0xffffffffu, pv[c][1], srcA);
                uint32_t u2 = __shfl_sync(0xffffffffu, pv[c][2], srcA);
                uint32_t u3 = __shfl_sync(0xffffffffu, pv[c][3], srcA);
                pa[0] = selOdd ? u1 : u0;
                pa[1] = selOdd ? u3 : u2;
                uint32_t v0 = __shfl_sync(0xffffffffu, pv[c][0], srcB);
                uint32_t v1 = __shfl_sync(0xffffffffu, pv[c][1], srcB);
                uint32_t v2 = __shfl_sync(0xffffffffu, pv[c][2], srcB);
                uint32_t v3 = __shfl_sync(0xffffffffu, pv[c][3], srcB);
                pa[2] = selOdd ? v1 : v0;
                pa[3] = selOdd ? v3 : v2;

                const int krow = wn * 16 + c * 8;   // this chunk's key rows
#pragma unroll
                for (int nt = 0; nt < 16; nt++) {
                    uint32_t bf[2];
                    bf[0] = Vb[(krow + tig) * VSTR + nt * 8 + g];
                    bf[1] = Vb[(krow + tig + 4) * VSTR + nt * 8 + g];
                    mma_tf32(acc[nt], pa, bf);
                }
            }
        }

        // ---- l reduction: quad shfl -> cross-wn via smem ----
#pragma unroll
        for (int off = 1; off <= 2; off <<= 1) {
            l0 += __shfl_xor_sync(0xffffffffu, l0, off);
            l1 += __shfl_xor_sync(0xffffffffu, l1, off);
        }
        if (tig == 0) {
            sRS[wn * 32 + wm * 16 + g]     = l0;
            sRS[wn * 32 + wm * 16 + g + 8] = l1;
        }

        // ---- O reduction: wn=1,2,3 dump partials; wn=0 sums ----
        if (wn > 0) {
            float* st = sStage + (wm * 3 + (wn - 1)) * 16 * RSTR;
#pragma unroll
            for (int nt = 0; nt < 16; nt++) {
                *(float2*)&st[g * RSTR + nt * 8 + tig * 2] =
                    make_float2(acc[nt][0], acc[nt][1]);
                *(float2*)&st[(g + 8) * RSTR + nt * 8 + tig * 2] =
                    make_float2(acc[nt][2], acc[nt][3]);
            }
        }
        __syncthreads();

        if (wn == 0) {
            float ts0 = sRS[wm * 16 + g], ts1 = sRS[wm * 16 + g + 8];
#pragma unroll
            for (int w = 1; w < 4; w++) {
                ts0 += sRS[w * 32 + wm * 16 + g];
                ts1 += sRS[w * 32 + wm * 16 + g + 8];
            }
#pragma unroll
            for (int s = 0; s < 3; s++) {
                float* st = sStage + (wm * 3 + s) * 16 * RSTR;
#pragma unroll
                for (int nt = 0; nt < 16; nt++) {
                    float2 lo = *(float2*)&st[g * RSTR + nt * 8 + tig * 2];
                    float2 hi = *(float2*)&st[(g + 8) * RSTR + nt * 8 + tig * 2];
                    acc[nt][0] += lo.x; acc[nt][1] += lo.y;
                    acc[nt][2] += hi.x; acc[nt][3] += hi.y;
                }
            }
            const float inv0 = 1.f / ts0;
            const float inv1 = 1.f / ts1;
#pragma unroll
            for (int nt = 0; nt < 16; nt++) {
                const int col = nt * 8 + tig * 2;
                *(float2*)(out + ((size_t)b * SS_ + row0) * HH + col) =
                    make_float2(acc[nt][0] * inv0, acc[nt][1] * inv0);
                *(float2*)(out + ((size_t)b * SS_ + row0 + 8) * HH + col) =
                    make_float2(acc[nt][2] * inv1, acc[nt][3] * inv1);
            }
        }
    }
}

// ---------------------------------------------------------------------------
extern "C" void kernel_launch(void* const* d_in, const int* in_sizes, int n_in,
                              void* d_out, int out_size)
{
    const float* x  = (const float*)d_in[0];
    const float* Wq = (const float*)d_in[1];
    const float* Wk = (const float*)d_in[2];
    const float* Wv = (const float*)d_in[3];
    float* out = (float*)d_out;

    cudaFuncSetAttribute(proj_mma_kernel, cudaFuncAttributeMaxDynamicSharedMemorySize,
                         PROJ_SMEM);
    cudaFuncSetAttribute(attn_tc_kernel, cudaFuncAttributeMaxDynamicSharedMemorySize,
                         ATT_SMEM);

    proj_mma_kernel<<<8192 / PBM, 256, PROJ_SMEM>>>(x, Wq, Wk, Wv);
    attn_tc_kernel<<<dim3(32, 4), 256, ATT_SMEM>>>(out);
}